// round 11
// baseline (speedup 1.0000x reference)
#include <cuda_runtime.h>
#include <cuda_bf16.h>
#include <cstdint>

#define BB   8
#define NN   4096
#define CC   512
#define HH   256
#define NCLS 1000
#define MTOT (BB*NN)   // 32768

// ---------------- device scratch ----------------
struct __align__(16) ZeroScratch {
    float prevsum[BB][CC];
    float v[BB][CC];
    float rowsum[MTOT];
    float rowsumsq[MTOT];
    float tb[BB];
    float Rb[BB];
};
__device__ ZeroScratch g_zs;

// ---------------- GEMM (fp32 in, bf16 MMA) with interleaved prev blocks ------
#define KC      16
#define NKC     32
#define STG     4
#define ROWF    96                    // 64B data + 32B pad: conflict-free LDS.64
#define MATB    (128 * ROWF)          // 12288
#define STAGE_BYTES (2 * MATB)        // 24576
#define SMEM_NEED (STG * STAGE_BYTES + 512)
#define NB_TOTAL 1536                 // 1024 gemm + 512 prev, interleaved 2:1

__device__ __forceinline__ uint32_t f2_to_bf2(float2 v) {
    uint32_t r;
    asm("cvt.rn.bf16x2.f32 %0, %1, %2;" : "=r"(r) : "f"(v.y), "f"(v.x));
    return r;
}

__global__ void __launch_bounds__(256, 2)
k_gemm(const float* __restrict__ A, const float* __restrict__ W,
       const float* __restrict__ pb, const float* __restrict__ prev) {
    extern __shared__ char sm[];
    const int tid = threadIdx.x;
    const int bid = blockIdx.x;

    if (bid % 3 == 2) {
        // ---- prev column-sum block (64 rows), interleaved with GEMM blocks ----
        int id = bid / 3;                     // 0..511
        int b = id >> 6;
        int n0 = (id & 63) * 64;
        int c4 = tid & 127;
        int rp = tid >> 7;
        const float4* p = (const float4*)(prev + ((size_t)(b * NN + n0 + rp)) * CC) + c4;
        float4 s = make_float4(0.f, 0.f, 0.f, 0.f);
#pragma unroll 8
        for (int i = 0; i < 32; i++) {
            float4 v = p[(size_t)i * 2 * (CC / 4)];
            s.x += v.x; s.y += v.y; s.z += v.z; s.w += v.w;
        }
        float4* sh = (float4*)sm;
        if (rp) sh[c4] = s;
        __syncthreads();
        if (!rp) {
            float4 o = sh[c4];
            atomicAdd(&g_zs.prevsum[b][4 * c4 + 0], s.x + o.x);
            atomicAdd(&g_zs.prevsum[b][4 * c4 + 1], s.y + o.y);
            atomicAdd(&g_zs.prevsum[b][4 * c4 + 2], s.z + o.z);
            atomicAdd(&g_zs.prevsum[b][4 * c4 + 3], s.w + o.w);
        }
        return;
    }

    // ---- GEMM block ----
    const int gid = (bid / 3) * 2 + (bid % 3);   // 0..1023
    float* pbs = (float*)(sm + STG * STAGE_BYTES);
    const int row0 = (gid >> 2) * 128;
    const int col0 = (gid & 3) * 128;
    if (tid < 128) pbs[tid] = pb[col0 + tid];

    uint32_t sbase;
    asm("{ .reg .u64 t; cvta.to.shared.u64 t, %1; cvt.u32.u64 %0, t; }"
        : "=r"(sbase) : "l"(sm));

    auto fill = [&](int j) {
        int stg = j & (STG - 1);
        int k0 = j * KC;
        uint32_t ab = sbase + stg * STAGE_BYTES;
        uint32_t bb = ab + MATB;
#pragma unroll
        for (int i = 0; i < 2; i++) {
            int id = tid + i * 256;           // 0..511
            int r = id >> 2, seg = id & 3;
            const float* sa = A + (size_t)(row0 + r) * CC + k0 + seg * 4;
            const float* sb = W + (size_t)(col0 + r) * CC + k0 + seg * 4;
            asm volatile("cp.async.cg.shared.global [%0], [%1], 16;"
                         :: "r"(ab + r * ROWF + seg * 16), "l"(sa));
            asm volatile("cp.async.cg.shared.global [%0], [%1], 16;"
                         :: "r"(bb + r * ROWF + seg * 16), "l"(sb));
        }
    };

#pragma unroll
    for (int j = 0; j < STG - 1; j++) {
        fill(j);
        asm volatile("cp.async.commit_group;");
    }

    const int warp = tid >> 5, lane = tid & 31;
    const int g = lane >> 2, q = lane & 3;
    const int wm = warp >> 1, wn = warp & 1;
    const int rbase = wm * 32, cbase = wn * 64;

    float acc[2][8][4];
#pragma unroll
    for (int mt = 0; mt < 2; mt++)
#pragma unroll
        for (int nt = 0; nt < 8; nt++)
#pragma unroll
            for (int j = 0; j < 4; j++) acc[mt][nt][j] = 0.f;

    for (int kc = 0; kc < NKC; kc++) {
        asm volatile("cp.async.wait_group %0;" :: "n"(STG - 2));
        __syncthreads();
        const char* as = sm + (kc & (STG - 1)) * STAGE_BYTES;
        const char* bs = as + MATB;
        const int kb = q * 8;

        uint32_t a[2][4], b[8][2];
#pragma unroll
        for (int mt = 0; mt < 2; mt++) {
            const char* r0p = as + (rbase + mt * 16 + g) * ROWF + kb;
            const char* r1p = r0p + 8 * ROWF;
            a[mt][0] = f2_to_bf2(*(const float2*)(r0p));
            a[mt][1] = f2_to_bf2(*(const float2*)(r1p));
            a[mt][2] = f2_to_bf2(*(const float2*)(r0p + 32));
            a[mt][3] = f2_to_bf2(*(const float2*)(r1p + 32));
        }
#pragma unroll
        for (int nt = 0; nt < 8; nt++) {
            const char* cp = bs + (cbase + nt * 8 + g) * ROWF + kb;
            b[nt][0] = f2_to_bf2(*(const float2*)(cp));
            b[nt][1] = f2_to_bf2(*(const float2*)(cp + 32));
        }
#pragma unroll
        for (int mt = 0; mt < 2; mt++)
#pragma unroll
            for (int nt = 0; nt < 8; nt++)
                asm volatile(
                    "mma.sync.aligned.m16n8k16.row.col.f32.bf16.bf16.f32 "
                    "{%0,%1,%2,%3},{%4,%5,%6,%7},{%8,%9},{%0,%1,%2,%3};"
                    : "+f"(acc[mt][nt][0]), "+f"(acc[mt][nt][1]),
                      "+f"(acc[mt][nt][2]), "+f"(acc[mt][nt][3])
                    : "r"(a[mt][0]), "r"(a[mt][1]), "r"(a[mt][2]), "r"(a[mt][3]),
                      "r"(b[nt][0]), "r"(b[nt][1]));
        __syncthreads();
        int jn = kc + STG - 1;
        if (jn < NKC) fill(jn);
        asm volatile("cp.async.commit_group;");
    }

#pragma unroll
    for (int mt = 0; mt < 2; mt++) {
        float s0 = 0.f, q0 = 0.f, s1 = 0.f, q1 = 0.f;
#pragma unroll
        for (int nt = 0; nt < 8; nt++) {
            float pb0 = pbs[cbase + nt * 8 + 2 * q];
            float pb1 = pbs[cbase + nt * 8 + 2 * q + 1];
            float v;
            v = acc[mt][nt][0] + pb0; s0 += v; q0 += v * v;
            v = acc[mt][nt][1] + pb1; s0 += v; q0 += v * v;
            v = acc[mt][nt][2] + pb0; s1 += v; q1 += v * v;
            v = acc[mt][nt][3] + pb1; s1 += v; q1 += v * v;
        }
#pragma unroll
        for (int off = 1; off < 4; off <<= 1) {
            s0 += __shfl_xor_sync(0xffffffffu, s0, off);
            q0 += __shfl_xor_sync(0xffffffffu, q0, off);
            s1 += __shfl_xor_sync(0xffffffffu, s1, off);
            q1 += __shfl_xor_sync(0xffffffffu, q1, off);
        }
        if (q == 0) {
            int r = row0 + rbase + mt * 16 + g;
            atomicAdd(&g_zs.rowsum[r],       s0);
            atomicAdd(&g_zs.rowsumsq[r],     q0);
            atomicAdd(&g_zs.rowsum[r + 8],   s1);
            atomicAdd(&g_zs.rowsumsq[r + 8], q1);
        }
    }
}

// ---------------- fused: rstd + v = sum_n rstd*feat (32 rows/block) ----------------
__global__ void __launch_bounds__(256)
k_vstats(const float* __restrict__ feat) {
    int b = blockIdx.y;
    int n0 = blockIdx.x * 32;
    int t = threadIdx.x;

    __shared__ float srstd[32];
    if (t < 32) {
        int r = b * NN + n0 + t;
        float mu  = g_zs.rowsum[r] * (1.f / CC);
        float var = g_zs.rowsumsq[r] * (1.f / CC) - mu * mu;
        float rstd = rsqrtf(var + 1e-5f);
        srstd[t] = rstd;
        float rm = rstd * mu;
#pragma unroll
        for (int off = 16; off > 0; off >>= 1) {
            rstd += __shfl_xor_sync(0xffffffffu, rstd, off);
            rm   += __shfl_xor_sync(0xffffffffu, rm, off);
        }
        if (t == 0) {
            atomicAdd(&g_zs.Rb[b], rstd);
            atomicAdd(&g_zs.tb[b], rm);
        }
    }
    __syncthreads();

    int c4 = t & 127;
    int rp = t >> 7;
    const float4* p = (const float4*)(feat + ((size_t)(b * NN + n0 + rp)) * CC) + c4;
    float4 s = make_float4(0.f, 0.f, 0.f, 0.f);
#pragma unroll
    for (int i = 0; i < 16; i++) {
        float w = srstd[2 * i + rp];
        float4 v = p[(size_t)i * 2 * (CC / 4)];
        s.x += w * v.x; s.y += w * v.y; s.z += w * v.z; s.w += w * v.w;
    }
    __shared__ float4 sh[128];
    if (rp) sh[c4] = s;
    __syncthreads();
    if (!rp) {
        float4 o = sh[c4];
        atomicAdd(&g_zs.v[b][4 * c4 + 0], s.x + o.x);
        atomicAdd(&g_zs.v[b][4 * c4 + 1], s.y + o.y);
        atomicAdd(&g_zs.v[b][4 * c4 + 2], s.z + o.z);
        atomicAdd(&g_zs.v[b][4 * c4 + 3], s.w + o.w);
    }
}

// ---------------- fused tail: pooled -> h1 -> h2 -> logits ----------------
// 16 blocks (2 per batch). Per-THREAD rows, float4, 2 accumulators: no
// shfl-serialized dots (the R4 failure mode). Redundant recompute of
// pooled/h1/h2 per block is ~0.6 MFLOP — trivial; weights are L2-warm.
__device__ __forceinline__ float dots(const float4* __restrict__ w4,
                                      const float4* __restrict__ x4, int n4) {
    float s0 = 0.f, s1 = 0.f;
#pragma unroll 8
    for (int i = 0; i < n4; i += 2) {
        float4 a = w4[i],     xa = x4[i];
        float4 b = w4[i + 1], xb = x4[i + 1];
        s0 += a.x * xa.x + a.y * xa.y + a.z * xa.z + a.w * xa.w;
        s1 += b.x * xb.x + b.y * xb.y + b.z * xb.z + b.w * xb.w;
    }
    return s0 + s1;
}

__global__ void __launch_bounds__(256)
k_tail(const float* __restrict__ W, const float* __restrict__ pb,
       const float* __restrict__ lng, const float* __restrict__ lnb,
       const float* __restrict__ W1, const float* __restrict__ b1,
       const float* __restrict__ W2, const float* __restrict__ b2,
       const float* __restrict__ W3, const float* __restrict__ b3,
       float* __restrict__ out) {
    __shared__ __align__(16) float sv[CC], sp[CC], sh1[HH], sh2[HH];
    const int t = threadIdx.x;
    const int b = blockIdx.x >> 1;
    const int half = blockIdx.x & 1;

    ((float2*)sv)[t] = ((const float2*)g_zs.v[b])[t];
    __syncthreads();
    const float Rb = g_zs.Rb[b], tb = g_zs.tb[b];

    // pooled: rows t and t+256
#pragma unroll
    for (int rr = 0; rr < 2; rr++) {
        int d = t + rr * 256;
        float s = dots((const float4*)(W + (size_t)d * CC), (const float4*)sv, CC / 4);
        float svv = s + Rb * pb[d] - tb;
        sp[d] = (g_zs.prevsum[b][d] + lng[d] * svv) * (1.f / NN) + lnb[d];
    }
    __syncthreads();

    // h1: row t
    {
        float s = dots((const float4*)(W1 + (size_t)t * CC), (const float4*)sp, CC / 4);
        sh1[t] = fmaxf(s + b1[t], 0.f);
    }
    __syncthreads();

    // h2: row t
    {
        float s = dots((const float4*)(W2 + (size_t)t * HH), (const float4*)sh1, HH / 4);
        sh2[t] = fmaxf(s + b2[t], 0.f);
    }
    __syncthreads();

    // logits: this block covers j in [half*500, half*500+500)
#pragma unroll
    for (int rr = 0; rr < 2; rr++) {
        int k = t + rr * 256;
        if (k < 500) {
            int j = half * 500 + k;
            float s = dots((const float4*)(W3 + (size_t)j * HH), (const float4*)sh2, HH / 4);
            out[b * NCLS + j] = s + b3[j];
        }
    }
}

// ---------------- launch ----------------
extern "C" void kernel_launch(void* const* d_in, const int* in_sizes, int n_in,
                              void* d_out, int out_size) {
    (void)in_sizes; (void)n_in; (void)out_size;
    const float* feat  = (const float*)d_in[0];
    const float* prev  = (const float*)d_in[1];
    // d_in[2], d_in[3] (positions) provably unused: gather is a row permutation
    // and all downstream consumers are permutation-invariant.
    const float* projW = (const float*)d_in[4];
    const float* projb = (const float*)d_in[5];
    const float* lng   = (const float*)d_in[6];
    const float* lnb   = (const float*)d_in[7];
    const float* W1    = (const float*)d_in[8];
    const float* b1    = (const float*)d_in[9];
    const float* W2    = (const float*)d_in[10];
    const float* b2    = (const float*)d_in[11];
    const float* W3    = (const float*)d_in[12];
    const float* b3    = (const float*)d_in[13];
    float* out = (float*)d_out;

    void* zs;
    cudaGetSymbolAddress(&zs, g_zs);

    cudaFuncSetAttribute(k_gemm, cudaFuncAttributeMaxDynamicSharedMemorySize,
                         SMEM_NEED);

    cudaMemsetAsync(zs, 0, sizeof(ZeroScratch));
    k_gemm<<<NB_TOTAL, 256, SMEM_NEED>>>(feat, projW, projb, prev);
    k_vstats<<<dim3(128, 8), 256>>>(feat);
    k_tail<<<2 * BB, 256>>>(projW, projb, lng, lnb, W1, b1, W2, b2, W3, b3, out);
}

// round 12
// speedup vs baseline: 1.6038x; 1.6038x over previous
#include <cuda_runtime.h>
#include <cuda_bf16.h>
#include <cstdint>

#define BB   8
#define NN   4096
#define CC   512
#define HH   256
#define NCLS 1000
#define MTOT (BB*NN)   // 32768

// ---------------- device scratch ----------------
struct __align__(16) ZeroScratch {
    float prevsum[BB][CC];
    float v[BB][CC];
    float rowsum[MTOT];
    float rowsumsq[MTOT];
    float tb[BB];
    float Rb[BB];
    int   c_pool, c_m1, c_m2;      // tail stage counters
};
__device__ ZeroScratch g_zs;

__device__ __align__(16) float g_pooled[BB][CC];
__device__ __align__(16) float g_h1[BB][HH];
__device__ __align__(16) float g_h2[BB][HH];

// ---------------- GEMM (fp32 in, bf16 MMA) + prev appended ----------------
#define KC      16
#define NKC     32
#define STG     4
#define ROWF    96                    // 64B data + 32B pad: conflict-free LDS.64
#define MATB    (128 * ROWF)          // 12288
#define STAGE_BYTES (2 * MATB)        // 24576
#define SMEM_NEED (STG * STAGE_BYTES + 512)
#define NB_GEMM 1024

__device__ __forceinline__ uint32_t f2_to_bf2(float2 v) {
    uint32_t r;
    asm("cvt.rn.bf16x2.f32 %0, %1, %2;" : "=r"(r) : "f"(v.y), "f"(v.x));
    return r;
}

__global__ void __launch_bounds__(256, 2)
k_gemm(const float* __restrict__ A, const float* __restrict__ W,
       const float* __restrict__ pb, const float* __restrict__ prev) {
    extern __shared__ char sm[];
    const int tid = threadIdx.x;

    if (blockIdx.x >= NB_GEMM) {
        // ---- prev column-sum block (64 rows), appended after GEMM blocks ----
        int id = blockIdx.x - NB_GEMM;        // 0..511
        int b = id >> 6;
        int n0 = (id & 63) * 64;
        int c4 = tid & 127;
        int rp = tid >> 7;
        const float4* p = (const float4*)(prev + ((size_t)(b * NN + n0 + rp)) * CC) + c4;
        float4 s = make_float4(0.f, 0.f, 0.f, 0.f);
#pragma unroll 8
        for (int i = 0; i < 32; i++) {
            float4 v = p[(size_t)i * 2 * (CC / 4)];
            s.x += v.x; s.y += v.y; s.z += v.z; s.w += v.w;
        }
        float4* sh = (float4*)sm;
        if (rp) sh[c4] = s;
        __syncthreads();
        if (!rp) {
            float4 o = sh[c4];
            atomicAdd(&g_zs.prevsum[b][4 * c4 + 0], s.x + o.x);
            atomicAdd(&g_zs.prevsum[b][4 * c4 + 1], s.y + o.y);
            atomicAdd(&g_zs.prevsum[b][4 * c4 + 2], s.z + o.z);
            atomicAdd(&g_zs.prevsum[b][4 * c4 + 3], s.w + o.w);
        }
        return;
    }

    // ---- GEMM block ----
    float* pbs = (float*)(sm + STG * STAGE_BYTES);
    const int row0 = (blockIdx.x >> 2) * 128;
    const int col0 = (blockIdx.x & 3) * 128;
    if (tid < 128) pbs[tid] = pb[col0 + tid];

    uint32_t sbase;
    asm("{ .reg .u64 t; cvta.to.shared.u64 t, %1; cvt.u32.u64 %0, t; }"
        : "=r"(sbase) : "l"(sm));

    auto fill = [&](int j) {
        int stg = j & (STG - 1);
        int k0 = j * KC;
        uint32_t ab = sbase + stg * STAGE_BYTES;
        uint32_t bb = ab + MATB;
#pragma unroll
        for (int i = 0; i < 2; i++) {
            int id = tid + i * 256;           // 0..511
            int r = id >> 2, seg = id & 3;
            const float* sa = A + (size_t)(row0 + r) * CC + k0 + seg * 4;
            const float* sb = W + (size_t)(col0 + r) * CC + k0 + seg * 4;
            asm volatile("cp.async.cg.shared.global [%0], [%1], 16;"
                         :: "r"(ab + r * ROWF + seg * 16), "l"(sa));
            asm volatile("cp.async.cg.shared.global [%0], [%1], 16;"
                         :: "r"(bb + r * ROWF + seg * 16), "l"(sb));
        }
    };

#pragma unroll
    for (int j = 0; j < STG - 1; j++) {
        fill(j);
        asm volatile("cp.async.commit_group;");
    }

    const int warp = tid >> 5, lane = tid & 31;
    const int g = lane >> 2, q = lane & 3;
    const int wm = warp >> 1, wn = warp & 1;
    const int rbase = wm * 32, cbase = wn * 64;

    float acc[2][8][4];
#pragma unroll
    for (int mt = 0; mt < 2; mt++)
#pragma unroll
        for (int nt = 0; nt < 8; nt++)
#pragma unroll
            for (int j = 0; j < 4; j++) acc[mt][nt][j] = 0.f;

    for (int kc = 0; kc < NKC; kc++) {
        asm volatile("cp.async.wait_group %0;" :: "n"(STG - 2));
        __syncthreads();
        const char* as = sm + (kc & (STG - 1)) * STAGE_BYTES;
        const char* bs = as + MATB;
        const int kb = q * 8;

        uint32_t a[2][4], b[8][2];
#pragma unroll
        for (int mt = 0; mt < 2; mt++) {
            const char* r0p = as + (rbase + mt * 16 + g) * ROWF + kb;
            const char* r1p = r0p + 8 * ROWF;
            a[mt][0] = f2_to_bf2(*(const float2*)(r0p));
            a[mt][1] = f2_to_bf2(*(const float2*)(r1p));
            a[mt][2] = f2_to_bf2(*(const float2*)(r0p + 32));
            a[mt][3] = f2_to_bf2(*(const float2*)(r1p + 32));
        }
#pragma unroll
        for (int nt = 0; nt < 8; nt++) {
            const char* cp = bs + (cbase + nt * 8 + g) * ROWF + kb;
            b[nt][0] = f2_to_bf2(*(const float2*)(cp));
            b[nt][1] = f2_to_bf2(*(const float2*)(cp + 32));
        }
#pragma unroll
        for (int mt = 0; mt < 2; mt++)
#pragma unroll
            for (int nt = 0; nt < 8; nt++)
                asm volatile(
                    "mma.sync.aligned.m16n8k16.row.col.f32.bf16.bf16.f32 "
                    "{%0,%1,%2,%3},{%4,%5,%6,%7},{%8,%9},{%0,%1,%2,%3};"
                    : "+f"(acc[mt][nt][0]), "+f"(acc[mt][nt][1]),
                      "+f"(acc[mt][nt][2]), "+f"(acc[mt][nt][3])
                    : "r"(a[mt][0]), "r"(a[mt][1]), "r"(a[mt][2]), "r"(a[mt][3]),
                      "r"(b[nt][0]), "r"(b[nt][1]));
        __syncthreads();
        int jn = kc + STG - 1;
        if (jn < NKC) fill(jn);
        asm volatile("cp.async.commit_group;");
    }

#pragma unroll
    for (int mt = 0; mt < 2; mt++) {
        float s0 = 0.f, q0 = 0.f, s1 = 0.f, q1 = 0.f;
#pragma unroll
        for (int nt = 0; nt < 8; nt++) {
            float pb0 = pbs[cbase + nt * 8 + 2 * q];
            float pb1 = pbs[cbase + nt * 8 + 2 * q + 1];
            float v;
            v = acc[mt][nt][0] + pb0; s0 += v; q0 += v * v;
            v = acc[mt][nt][1] + pb1; s0 += v; q0 += v * v;
            v = acc[mt][nt][2] + pb0; s1 += v; q1 += v * v;
            v = acc[mt][nt][3] + pb1; s1 += v; q1 += v * v;
        }
#pragma unroll
        for (int off = 1; off < 4; off <<= 1) {
            s0 += __shfl_xor_sync(0xffffffffu, s0, off);
            q0 += __shfl_xor_sync(0xffffffffu, q0, off);
            s1 += __shfl_xor_sync(0xffffffffu, s1, off);
            q1 += __shfl_xor_sync(0xffffffffu, q1, off);
        }
        if (q == 0) {
            int r = row0 + rbase + mt * 16 + g;
            atomicAdd(&g_zs.rowsum[r],       s0);
            atomicAdd(&g_zs.rowsumsq[r],     q0);
            atomicAdd(&g_zs.rowsum[r + 8],   s1);
            atomicAdd(&g_zs.rowsumsq[r + 8], q1);
        }
    }
}

// ---------------- fused: rstd + v = sum_n rstd*feat (32 rows/block) ----------------
__global__ void __launch_bounds__(256)
k_vstats(const float* __restrict__ feat) {
    int b = blockIdx.y;
    int n0 = blockIdx.x * 32;
    int t = threadIdx.x;

    __shared__ float srstd[32];
    if (t < 32) {
        int r = b * NN + n0 + t;
        float mu  = g_zs.rowsum[r] * (1.f / CC);
        float var = g_zs.rowsumsq[r] * (1.f / CC) - mu * mu;
        float rstd = rsqrtf(var + 1e-5f);
        srstd[t] = rstd;
        float rm = rstd * mu;
#pragma unroll
        for (int off = 16; off > 0; off >>= 1) {
            rstd += __shfl_xor_sync(0xffffffffu, rstd, off);
            rm   += __shfl_xor_sync(0xffffffffu, rm, off);
        }
        if (t == 0) {
            atomicAdd(&g_zs.Rb[b], rstd);
            atomicAdd(&g_zs.tb[b], rm);
        }
    }
    __syncthreads();

    int c4 = t & 127;
    int rp = t >> 7;
    const float4* p = (const float4*)(feat + ((size_t)(b * NN + n0 + rp)) * CC) + c4;
    float4 s = make_float4(0.f, 0.f, 0.f, 0.f);
#pragma unroll
    for (int i = 0; i < 16; i++) {
        float w = srstd[2 * i + rp];
        float4 v = p[(size_t)i * 2 * (CC / 4)];
        s.x += w * v.x; s.y += w * v.y; s.z += w * v.z; s.w += w * v.w;
    }
    __shared__ float4 sh[128];
    if (rp) sh[c4] = s;
    __syncthreads();
    if (!rp) {
        float4 o = sh[c4];
        atomicAdd(&g_zs.v[b][4 * c4 + 0], s.x + o.x);
        atomicAdd(&g_zs.v[b][4 * c4 + 1], s.y + o.y);
        atomicAdd(&g_zs.v[b][4 * c4 + 2], s.z + o.z);
        atomicAdd(&g_zs.v[b][4 * c4 + 3], s.w + o.w);
    }
}

// ---------------- fused tail: proven warp-per-row GEMVs, counter-chained ----
__device__ __forceinline__ float dot512(const float4* __restrict__ w4,
                                        const float4* __restrict__ x4, int lane) {
    float s = 0.f;
#pragma unroll
    for (int i = 0; i < 4; i++) {
        float4 a = w4[lane + 32 * i];
        float4 b = x4[lane + 32 * i];
        s += a.x * b.x + a.y * b.y + a.z * b.z + a.w * b.w;
    }
#pragma unroll
    for (int off = 16; off > 0; off >>= 1) s += __shfl_xor_sync(0xffffffffu, s, off);
    return s;
}
__device__ __forceinline__ float dot256(const float4* __restrict__ w4,
                                        const float4* __restrict__ x4, int lane) {
    float s = 0.f;
#pragma unroll
    for (int i = 0; i < 2; i++) {
        float4 a = w4[lane + 32 * i];
        float4 b = x4[lane + 32 * i];
        s += a.x * b.x + a.y * b.y + a.z * b.z + a.w * b.w;
    }
#pragma unroll
    for (int off = 16; off > 0; off >>= 1) s += __shfl_xor_sync(0xffffffffu, s, off);
    return s;
}

__device__ __forceinline__ void stage_done(int* ctr) {
    __threadfence();
    __syncthreads();
    if (threadIdx.x == 0) atomicAdd(ctr, 1);
}
__device__ __forceinline__ void stage_wait(int* ctr, int need) {
    if (threadIdx.x == 0) {
        while (*(volatile int*)ctr < need) __nanosleep(64);
    }
    __syncthreads();
    __threadfence();
}

#define TB_POOL 512
#define TB_M1   256
#define TB_M2   256
#define TB_M3   1000
#define NB_TAIL (TB_POOL + TB_M1 + TB_M2 + TB_M3)   // 2024

__global__ void __launch_bounds__(256)
k_tail(const float* __restrict__ W, const float* __restrict__ pb,
       const float* __restrict__ lng, const float* __restrict__ lnb,
       const float* __restrict__ W1, const float* __restrict__ b1,
       const float* __restrict__ W2, const float* __restrict__ b2,
       const float* __restrict__ W3, const float* __restrict__ b3,
       float* __restrict__ out) {
    const int bid = blockIdx.x;
    const int lane = threadIdx.x & 31;
    const int wid = threadIdx.x >> 5;

    if (bid < TB_POOL) {
        // pooled: 512 blocks x 8 warps = 4096 (b,d) pairs  (never spins)
        int warp = bid * 8 + wid;
        int b = warp >> 9, d = warp & 511;
        float s = dot512((const float4*)(W + (size_t)d * CC), (const float4*)g_zs.v[b], lane);
        if (lane == 0) {
            float sv = s + g_zs.Rb[b] * pb[d] - g_zs.tb[b];
            g_pooled[b][d] = (g_zs.prevsum[b][d] + lng[d] * sv) * (1.f / NN) + lnb[d];
        }
        stage_done(&g_zs.c_pool);
    } else if (bid < TB_POOL + TB_M1) {
        stage_wait(&g_zs.c_pool, TB_POOL);
        int warp = (bid - TB_POOL) * 8 + wid;       // 0..2047
        int b = warp >> 8, i = warp & 255;
        float s = dot512((const float4*)(W1 + (size_t)i * CC), (const float4*)g_pooled[b], lane);
        if (lane == 0) g_h1[b][i] = fmaxf(s + b1[i], 0.f);
        stage_done(&g_zs.c_m1);
    } else if (bid < TB_POOL + TB_M1 + TB_M2) {
        stage_wait(&g_zs.c_m1, TB_M1);
        int warp = (bid - TB_POOL - TB_M1) * 8 + wid;
        int b = warp >> 8, i = warp & 255;
        float s = dot256((const float4*)(W2 + (size_t)i * HH), (const float4*)g_h1[b], lane);
        if (lane == 0) g_h2[b][i] = fmaxf(s + b2[i], 0.f);
        stage_done(&g_zs.c_m2);
    } else {
        stage_wait(&g_zs.c_m2, TB_M2);
        int warp = (bid - TB_POOL - TB_M1 - TB_M2) * 8 + wid;   // 0..7999
        int b = warp / NCLS, j = warp % NCLS;
        float s = dot256((const float4*)(W3 + (size_t)j * HH), (const float4*)g_h2[b], lane);
        if (lane == 0) out[b * NCLS + j] = s + b3[j];
    }
}

// ---------------- launch ----------------
extern "C" void kernel_launch(void* const* d_in, const int* in_sizes, int n_in,
                              void* d_out, int out_size) {
    (void)in_sizes; (void)n_in; (void)out_size;
    const float* feat  = (const float*)d_in[0];
    const float* prev  = (const float*)d_in[1];
    // d_in[2], d_in[3] (positions) provably unused: gather is a row permutation
    // and all downstream consumers are permutation-invariant.
    const float* projW = (const float*)d_in[4];
    const float* projb = (const float*)d_in[5];
    const float* lng   = (const float*)d_in[6];
    const float* lnb   = (const float*)d_in[7];
    const float* W1    = (const float*)d_in[8];
    const float* b1    = (const float*)d_in[9];
    const float* W2    = (const float*)d_in[10];
    const float* b2    = (const float*)d_in[11];
    const float* W3    = (const float*)d_in[12];
    const float* b3    = (const float*)d_in[13];
    float* out = (float*)d_out;

    void* zs;
    cudaGetSymbolAddress(&zs, g_zs);

    cudaFuncSetAttribute(k_gemm, cudaFuncAttributeMaxDynamicSharedMemorySize,
                         SMEM_NEED);

    cudaMemsetAsync(zs, 0, sizeof(ZeroScratch));
    k_gemm<<<NB_GEMM + 512, 256, SMEM_NEED>>>(feat, projW, projb, prev);
    k_vstats<<<dim3(128, 8), 256>>>(feat);
    k_tail<<<NB_TAIL, 256>>>(projW, projb, lng, lnb, W1, b1, W2, b2, W3, b3, out);
}

// round 14
// speedup vs baseline: 1.7987x; 1.1216x over previous
#include <cuda_runtime.h>
#include <cuda_bf16.h>
#include <cstdint>

#define BB   8
#define NN   4096
#define CC   512
#define HH   256
#define NCLS 1000
#define MTOT (BB*NN)   // 32768

// ---------------- device scratch ----------------
__device__ __align__(16) __nv_bfloat16 g_featb[(size_t)MTOT * CC];  // 32 MB
__device__ __align__(16) __nv_bfloat16 g_Wb[(size_t)CC * CC];       // 512 KB

struct __align__(16) ZeroScratch {
    float prevsum[BB][CC];
    float v[BB][CC];
    float rowsum[MTOT];
    float rowsumsq[MTOT];
    float tb[BB];
    float Rb[BB];
};
__device__ ZeroScratch g_zs;

__device__ __align__(16) float g_pooled[BB][CC];
__device__ __align__(16) float g_h1[BB][HH];
__device__ __align__(16) float g_h2[BB][HH];

// ---------------- front: cvt(feat) + cvt(W) ----------------
#define NB_CVTF 16384
#define NB_CVTW 256
#define NB_FRONT (NB_CVTF + NB_CVTW)

__global__ void __launch_bounds__(256)
k_front(const float* __restrict__ feat, const float* __restrict__ projW) {
    int blk = blockIdx.x;
    int t = threadIdx.x;
    if (blk < NB_CVTF) {
        int i = blk * 256 + t;
        float4 v = ((const float4*)feat)[i];
        ((__nv_bfloat162*)g_featb)[2 * i]     = __floats2bfloat162_rn(v.x, v.y);
        ((__nv_bfloat162*)g_featb)[2 * i + 1] = __floats2bfloat162_rn(v.z, v.w);
    } else {
        int i = (blk - NB_CVTF) * 256 + t;
        float4 v = ((const float4*)projW)[i];
        ((__nv_bfloat162*)g_Wb)[2 * i]     = __floats2bfloat162_rn(v.x, v.y);
        ((__nv_bfloat162*)g_Wb)[2 * i + 1] = __floats2bfloat162_rn(v.z, v.w);
    }
}

// ---------------- bf16 GEMM with ldmatrix fragments + prev appended --------
#define KC    32
#define NKC   16
#define STG   5
#define ROWB  80                      // 64B bf16 data + 16B pad
#define MATB  (128 * ROWB)            // 10240
#define STAGE_BYTES (2 * MATB)        // 20480
#define SMEM_NEED (STG * STAGE_BYTES + 512)
#define NB_GEMM 1024

__device__ __forceinline__ void ldsm4(uint32_t& r0, uint32_t& r1,
                                      uint32_t& r2, uint32_t& r3, uint32_t addr) {
    asm volatile("ldmatrix.sync.aligned.m8n8.x4.shared.b16 {%0,%1,%2,%3}, [%4];"
                 : "=r"(r0), "=r"(r1), "=r"(r2), "=r"(r3) : "r"(addr));
}

__global__ void __launch_bounds__(256, 2)
k_gemm(const float* __restrict__ pb, const float* __restrict__ prev) {
    extern __shared__ char sm[];
    const int tid = threadIdx.x;

    if (blockIdx.x >= NB_GEMM) {
        // ---- prev column-sum block (64 rows), appended after GEMM blocks ----
        int id = blockIdx.x - NB_GEMM;        // 0..511
        int b = id >> 6;
        int n0 = (id & 63) * 64;
        int c4 = tid & 127;
        int rp = tid >> 7;
        const float4* p = (const float4*)(prev + ((size_t)(b * NN + n0 + rp)) * CC) + c4;
        float4 s = make_float4(0.f, 0.f, 0.f, 0.f);
#pragma unroll 8
        for (int i = 0; i < 32; i++) {
            float4 v = p[(size_t)i * 2 * (CC / 4)];
            s.x += v.x; s.y += v.y; s.z += v.z; s.w += v.w;
        }
        float4* sh = (float4*)sm;
        if (rp) sh[c4] = s;
        __syncthreads();
        if (!rp) {
            float4 o = sh[c4];
            atomicAdd(&g_zs.prevsum[b][4 * c4 + 0], s.x + o.x);
            atomicAdd(&g_zs.prevsum[b][4 * c4 + 1], s.y + o.y);
            atomicAdd(&g_zs.prevsum[b][4 * c4 + 2], s.z + o.z);
            atomicAdd(&g_zs.prevsum[b][4 * c4 + 3], s.w + o.w);
        }
        return;
    }

    // ---- GEMM block ----
    float* pbs = (float*)(sm + STG * STAGE_BYTES);
    const int row0 = (blockIdx.x >> 2) * 128;
    const int col0 = (blockIdx.x & 3) * 128;
    if (tid < 128) pbs[tid] = pb[col0 + tid];

    uint32_t sbase;
    asm("{ .reg .u64 t; cvta.to.shared.u64 t, %1; cvt.u32.u64 %0, t; }"
        : "=r"(sbase) : "l"(sm));

    auto fill = [&](int j) {
        int stg = j % STG;
        int k0 = j * KC;
        uint32_t ab = sbase + stg * STAGE_BYTES;
        uint32_t bb = ab + MATB;
#pragma unroll
        for (int i = 0; i < 2; i++) {
            int id = tid + i * 256;           // 0..511
            int r = id >> 2, seg = id & 3;
            const __nv_bfloat16* sa = g_featb + (size_t)(row0 + r) * CC + k0 + seg * 8;
            const __nv_bfloat16* sb = g_Wb   + (size_t)(col0 + r) * CC + k0 + seg * 8;
            asm volatile("cp.async.cg.shared.global [%0], [%1], 16;"
                         :: "r"(ab + r * ROWB + seg * 16), "l"(sa));
            asm volatile("cp.async.cg.shared.global [%0], [%1], 16;"
                         :: "r"(bb + r * ROWB + seg * 16), "l"(sb));
        }
    };

#pragma unroll
    for (int j = 0; j < STG - 1; j++) {
        fill(j);
        asm volatile("cp.async.commit_group;");
    }

    const int warp = tid >> 5, lane = tid & 31;
    const int g = lane >> 2, q = lane & 3;
    const int wm = warp >> 1, wn = warp & 1;
    const int rbase = wm * 32, cbase = wn * 64;

    // ldmatrix lane-address offsets (within a stage)
    const int lrow = lane & 7, lsel = lane >> 3;
    uint32_t offA0 = (uint32_t)((rbase + lrow + (lsel & 1) * 8) * ROWB + (lsel >> 1) * 16);
    uint32_t offA1 = offA0 + 16 * ROWB;
    uint32_t offB[4];
#pragma unroll
    for (int p = 0; p < 4; p++)
        offB[p] = (uint32_t)((cbase + (2 * p + (lsel >> 1)) * 8 + lrow) * ROWB
                             + (lsel & 1) * 16);

    float acc[2][8][4];
#pragma unroll
    for (int mt = 0; mt < 2; mt++)
#pragma unroll
        for (int nt = 0; nt < 8; nt++)
#pragma unroll
            for (int j = 0; j < 4; j++) acc[mt][nt][j] = 0.f;

    for (int kc = 0; kc < NKC; kc++) {
        asm volatile("cp.async.wait_group %0;" :: "n"(STG - 2));
        __syncthreads();
        uint32_t ab = sbase + (uint32_t)((kc % STG) * STAGE_BYTES);
        uint32_t bb = ab + MATB;
#pragma unroll
        for (int kt = 0; kt < 2; kt++) {
            uint32_t ko = kt * 32;
            uint32_t a[2][4], b[8][2];
            ldsm4(a[0][0], a[0][1], a[0][2], a[0][3], ab + offA0 + ko);
            ldsm4(a[1][0], a[1][1], a[1][2], a[1][3], ab + offA1 + ko);
#pragma unroll
            for (int p = 0; p < 4; p++)
                ldsm4(b[2 * p][0], b[2 * p][1], b[2 * p + 1][0], b[2 * p + 1][1],
                      bb + offB[p] + ko);
#pragma unroll
            for (int mt = 0; mt < 2; mt++)
#pragma unroll
                for (int nt = 0; nt < 8; nt++)
                    asm volatile(
                        "mma.sync.aligned.m16n8k16.row.col.f32.bf16.bf16.f32 "
                        "{%0,%1,%2,%3},{%4,%5,%6,%7},{%8,%9},{%0,%1,%2,%3};"
                        : "+f"(acc[mt][nt][0]), "+f"(acc[mt][nt][1]),
                          "+f"(acc[mt][nt][2]), "+f"(acc[mt][nt][3])
                        : "r"(a[mt][0]), "r"(a[mt][1]), "r"(a[mt][2]), "r"(a[mt][3]),
                          "r"(b[nt][0]), "r"(b[nt][1]));
        }
        __syncthreads();
        int jn = kc + STG - 1;
        if (jn < NKC) fill(jn);
        asm volatile("cp.async.commit_group;");
    }

#pragma unroll
    for (int mt = 0; mt < 2; mt++) {
        float s0 = 0.f, q0 = 0.f, s1 = 0.f, q1 = 0.f;
#pragma unroll
        for (int nt = 0; nt < 8; nt++) {
            float pb0 = pbs[cbase + nt * 8 + 2 * q];
            float pb1 = pbs[cbase + nt * 8 + 2 * q + 1];
            float v;
            v = acc[mt][nt][0] + pb0; s0 += v; q0 += v * v;
            v = acc[mt][nt][1] + pb1; s0 += v; q0 += v * v;
            v = acc[mt][nt][2] + pb0; s1 += v; q1 += v * v;
            v = acc[mt][nt][3] + pb1; s1 += v; q1 += v * v;
        }
#pragma unroll
        for (int off = 1; off < 4; off <<= 1) {
            s0 += __shfl_xor_sync(0xffffffffu, s0, off);
            q0 += __shfl_xor_sync(0xffffffffu, q0, off);
            s1 += __shfl_xor_sync(0xffffffffu, s1, off);
            q1 += __shfl_xor_sync(0xffffffffu, q1, off);
        }
        if (q == 0) {
            int r = row0 + rbase + mt * 16 + g;
            atomicAdd(&g_zs.rowsum[r],       s0);
            atomicAdd(&g_zs.rowsumsq[r],     q0);
            atomicAdd(&g_zs.rowsum[r + 8],   s1);
            atomicAdd(&g_zs.rowsumsq[r + 8], q1);
        }
    }
}

// ---------------- fused: rstd + v = sum_n rstd*feat (32 rows/block) ----------------
__global__ void __launch_bounds__(256)
k_vstats(const float* __restrict__ feat) {
    int b = blockIdx.y;
    int n0 = blockIdx.x * 32;
    int t = threadIdx.x;

    __shared__ float srstd[32];
    if (t < 32) {
        int r = b * NN + n0 + t;
        float mu  = g_zs.rowsum[r] * (1.f / CC);
        float var = g_zs.rowsumsq[r] * (1.f / CC) - mu * mu;
        float rstd = rsqrtf(var + 1e-5f);
        srstd[t] = rstd;
        float rm = rstd * mu;
#pragma unroll
        for (int off = 16; off > 0; off >>= 1) {
            rstd += __shfl_xor_sync(0xffffffffu, rstd, off);
            rm   += __shfl_xor_sync(0xffffffffu, rm, off);
        }
        if (t == 0) {
            atomicAdd(&g_zs.Rb[b], rstd);
            atomicAdd(&g_zs.tb[b], rm);
        }
    }
    __syncthreads();

    int c4 = t & 127;
    int rp = t >> 7;
    const float4* p = (const float4*)(feat + ((size_t)(b * NN + n0 + rp)) * CC) + c4;
    float4 s = make_float4(0.f, 0.f, 0.f, 0.f);
#pragma unroll
    for (int i = 0; i < 16; i++) {
        float w = srstd[2 * i + rp];
        float4 v = p[(size_t)i * 2 * (CC / 4)];
        s.x += w * v.x; s.y += w * v.y; s.z += w * v.z; s.w += w * v.w;
    }
    __shared__ float4 sh[128];
    if (rp) sh[c4] = s;
    __syncthreads();
    if (!rp) {
        float4 o = sh[c4];
        atomicAdd(&g_zs.v[b][4 * c4 + 0], s.x + o.x);
        atomicAdd(&g_zs.v[b][4 * c4 + 1], s.y + o.y);
        atomicAdd(&g_zs.v[b][4 * c4 + 2], s.z + o.z);
        atomicAdd(&g_zs.v[b][4 * c4 + 3], s.w + o.w);
    }
}

// ---------------- tail GEMVs (proven warp-per-row, float4) ----------------
__device__ __forceinline__ float dot512(const float4* __restrict__ w4,
                                        const float4* __restrict__ x4, int lane) {
    float s = 0.f;
#pragma unroll
    for (int i = 0; i < 4; i++) {
        float4 a = w4[lane + 32 * i];
        float4 b = x4[lane + 32 * i];
        s += a.x * b.x + a.y * b.y + a.z * b.z + a.w * b.w;
    }
#pragma unroll
    for (int off = 16; off > 0; off >>= 1) s += __shfl_xor_sync(0xffffffffu, s, off);
    return s;
}
__device__ __forceinline__ float dot256(const float4* __restrict__ w4,
                                        const float4* __restrict__ x4, int lane) {
    float s = 0.f;
#pragma unroll
    for (int i = 0; i < 2; i++) {
        float4 a = w4[lane + 32 * i];
        float4 b = x4[lane + 32 * i];
        s += a.x * b.x + a.y * b.y + a.z * b.z + a.w * b.w;
    }
#pragma unroll
    for (int off = 16; off > 0; off >>= 1) s += __shfl_xor_sync(0xffffffffu, s, off);
    return s;
}

__global__ void k_pool(const float* __restrict__ W, const float* __restrict__ pb,
                       const float* __restrict__ lng, const float* __restrict__ lnb) {
    int warp = blockIdx.x * 8 + (threadIdx.x >> 5);   // 0..4095
    int lane = threadIdx.x & 31;
    int b = warp >> 9;
    int d = warp & 511;
    float s = dot512((const float4*)(W + (size_t)d * CC), (const float4*)g_zs.v[b], lane);
    if (lane == 0) {
        float sv = s + g_zs.Rb[b] * pb[d] - g_zs.tb[b];
        g_pooled[b][d] = (g_zs.prevsum[b][d] + lng[d] * sv) * (1.f / NN) + lnb[d];
    }
}

__global__ void k_mlp1(const float* __restrict__ W1, const float* __restrict__ b1) {
    int warp = blockIdx.x * 8 + (threadIdx.x >> 5);   // 0..2047
    int lane = threadIdx.x & 31;
    int b = warp >> 8, i = warp & 255;
    float s = dot512((const float4*)(W1 + (size_t)i * CC), (const float4*)g_pooled[b], lane);
    if (lane == 0) g_h1[b][i] = fmaxf(s + b1[i], 0.f);
}

__global__ void k_mlp2(const float* __restrict__ W2, const float* __restrict__ b2) {
    int warp = blockIdx.x * 8 + (threadIdx.x >> 5);
    int lane = threadIdx.x & 31;
    int b = warp >> 8, i = warp & 255;
    float s = dot256((const float4*)(W2 + (size_t)i * HH), (const float4*)g_h1[b], lane);
    if (lane == 0) g_h2[b][i] = fmaxf(s + b2[i], 0.f);
}

__global__ void k_mlp3(const float* __restrict__ W3, const float* __restrict__ b3,
                       float* __restrict__ out) {
    int warp = blockIdx.x * 8 + (threadIdx.x >> 5);   // 0..7999
    int lane = threadIdx.x & 31;
    int b = warp / NCLS, j = warp % NCLS;
    float s = dot256((const float4*)(W3 + (size_t)j * HH), (const float4*)g_h2[b], lane);
    if (lane == 0) out[b * NCLS + j] = s + b3[j];
}

// ---------------- launch ----------------
extern "C" void kernel_launch(void* const* d_in, const int* in_sizes, int n_in,
                              void* d_out, int out_size) {
    (void)in_sizes; (void)n_in; (void)out_size;
    const float* feat  = (const float*)d_in[0];
    const float* prev  = (const float*)d_in[1];
    // d_in[2], d_in[3] (positions) provably unused: gather is a row permutation
    // and all downstream consumers are permutation-invariant.
    const float* projW = (const float*)d_in[4];
    const float* projb = (const float*)d_in[5];
    const float* lng   = (const float*)d_in[6];
    const float* lnb   = (const float*)d_in[7];
    const float* W1    = (const float*)d_in[8];
    const float* b1    = (const float*)d_in[9];
    const float* W2    = (const float*)d_in[10];
    const float* b2    = (const float*)d_in[11];
    const float* W3    = (const float*)d_in[12];
    const float* b3    = (const float*)d_in[13];
    float* out = (float*)d_out;

    void* zs;
    cudaGetSymbolAddress(&zs, g_zs);

    cudaFuncSetAttribute(k_gemm, cudaFuncAttributeMaxDynamicSharedMemorySize,
                         SMEM_NEED);

    cudaMemsetAsync(zs, 0, sizeof(ZeroScratch));
    k_front<<<NB_FRONT, 256>>>(feat, projW);
    k_gemm<<<NB_GEMM + 512, 256, SMEM_NEED>>>(projb, prev);
    k_vstats<<<dim3(128, 8), 256>>>(feat);
    k_pool<<<512, 256>>>(projW, projb, lng, lnb);
    k_mlp1<<<256, 256>>>(W1, b1);
    k_mlp2<<<256, 256>>>(W2, b2);
    k_mlp3<<<1000, 256>>>(W3, b3, out);
}